// round 12
// baseline (speedup 1.0000x reference)
#include <cuda_runtime.h>
#include <cuda_bf16.h>
#include <cstdint>

// Problem constants (fixed by the reference):
//   N_NODES = 100000, IN_F = 256, OUT_F = 128, N_EDGES = 1600000
// Inputs (metadata order): X_input[f32 N*256], adj_row[i32 E], adj_col[i32 E],
//                          adj_val[f32 E], W[f32 256*128], bias[f32 128]
// Output: f32 [N, 128]

#define MAX_NODES 100000
#define IN_F      256
#define OUT_F     128

// Scratch for support = X @ W  (51.2 MB). Static __device__ per harness rules.
__device__ __align__(16) float g_support[(size_t)MAX_NODES * OUT_F];

// ---------------------------------------------------------------------------
// Kernel 1: SGEMM  S[M,128] = X[M,256] @ W[256,128]
// 128x128 block tile, BK=16, 256 threads. Same simple loop as the 322us
// baseline (LDG -> STS -> sync -> compute -> sync); ONLY the fragment
// mapping changed:
//   warp grid 4(m) x 2(n), lane grid 4(m) x 8(n), split-half micro-tile
//   rows rbase+{0..3}, rbase+16+{0..3}; cols cbase+{0..3}, cbase+32+{0..3}.
// Every frag load is a contiguous 64B/128B LDS.128 span with broadcast ->
// conflict-free (old trow*8 / tcol*8 mapping was 4-way conflicted on BOTH
// frags: that was the fma=48% @ issue=62% signature).
// ---------------------------------------------------------------------------
#define BM 128
#define BN 128
#define BK 16
#define ASTRIDE (BM + 4)

__global__ __launch_bounds__(256, 2)
void gemm_kernel(const float* __restrict__ X, const float* __restrict__ W,
                 float* __restrict__ S, int M) {
    __shared__ float As[BK][ASTRIDE];   // K-major A tile (transposed on STS)
    __shared__ float Bs[BK][BN];

    const int tid  = threadIdx.x;
    const int row0 = blockIdx.x * BM;
    const int warp = tid >> 5, lane = tid & 31;
    const int warp_m = warp & 3, warp_n = warp >> 2;   // 4 x 2 warps
    const int lane_m = lane & 3, lane_n = lane >> 2;   // 4 x 8 lanes
    const int rbase = warp_m * 32 + lane_m * 4;
    const int cbase = warp_n * 64 + lane_n * 4;

    float acc[8][8];
#pragma unroll
    for (int i = 0; i < 8; i++)
#pragma unroll
        for (int j = 0; j < 8; j++) acc[i][j] = 0.0f;

    for (int k0 = 0; k0 < IN_F; k0 += BK) {
        // ---- load A tile: 128 rows x 16 cols = 512 float4, 2 per thread ----
        // 4 consecutive tids cover one row's 64B chunk -> coalesced LDG.
#pragma unroll
        for (int i = 0; i < 2; i++) {
            int f   = tid + i * 256;        // float4 index in tile
            int ar  = f >> 2;               // tile row 0..127
            int ac4 = f & 3;                // float4 within row 0..3
            int grow = row0 + ar;
            if (grow >= M) grow = M - 1;    // clamp: duplicate load, never stored
            float4 v = *(const float4*)(X + (size_t)grow * IN_F + k0 + ac4 * 4);
            As[ac4 * 4 + 0][ar] = v.x;
            As[ac4 * 4 + 1][ar] = v.y;
            As[ac4 * 4 + 2][ar] = v.z;
            As[ac4 * 4 + 3][ar] = v.w;
        }
        // ---- load B tile: 16 rows x 128 cols = 512 float4, 2 per thread ----
#pragma unroll
        for (int i = 0; i < 2; i++) {
            int f   = tid + i * 256;
            int br  = f >> 5;               // 0..15
            int bc4 = f & 31;               // 0..31
            float4 v = *(const float4*)(W + (size_t)(k0 + br) * OUT_F + bc4 * 4);
            *(float4*)&Bs[br][bc4 * 4] = v;
        }
        __syncthreads();

#pragma unroll
        for (int k = 0; k < BK; k++) {
            float4 a0 = *(const float4*)&As[k][rbase];        // 64B span, bcast
            float4 a1 = *(const float4*)&As[k][rbase + 16];
            float4 b0 = *(const float4*)&Bs[k][cbase];        // 128B span, bcast
            float4 b1 = *(const float4*)&Bs[k][cbase + 32];
            float av[8] = {a0.x, a0.y, a0.z, a0.w, a1.x, a1.y, a1.z, a1.w};
            float bv[8] = {b0.x, b0.y, b0.z, b0.w, b1.x, b1.y, b1.z, b1.w};
#pragma unroll
            for (int i = 0; i < 8; i++)
#pragma unroll
                for (int j = 0; j < 8; j++)
                    acc[i][j] = fmaf(av[i], bv[j], acc[i][j]);
        }
        __syncthreads();
    }

    // ---- store: split-half rows/cols, two float4 per row ----
#pragma unroll
    for (int i = 0; i < 8; i++) {
        int r = row0 + rbase + (i < 4 ? i : 12 + i);   // +{0..3}, +16+{0..3}
        if (r < M) {
            float4 o0 = make_float4(acc[i][0], acc[i][1], acc[i][2], acc[i][3]);
            float4 o1 = make_float4(acc[i][4], acc[i][5], acc[i][6], acc[i][7]);
            float* dst = S + (size_t)r * OUT_F;
            *(float4*)(dst + cbase)      = o0;
            *(float4*)(dst + cbase + 32) = o1;
        }
    }
}

// ---------------------------------------------------------------------------
// Kernel 2: out[n, :] = bias  (broadcast init; out is poisoned by harness)
// ---------------------------------------------------------------------------
__global__ __launch_bounds__(256)
void init_out_kernel(float* __restrict__ out, const float* __restrict__ bias,
                     int n4) {
    int i = blockIdx.x * blockDim.x + threadIdx.x;
    if (i < n4) {
        float4 b = __ldg((const float4*)bias + (i & 31));
        ((float4*)out)[i] = b;
    }
}

// ---------------------------------------------------------------------------
// Kernel 3: COO SpMM (known-good from the 322us run).
// One warp per edge: 32 lanes x float4 = 128 floats (full row).
// 4 edges per warp -> MLP=4 on gathers; support (51.2 MB) is L2-resident.
// red.global.add.v4.f32 = no-return atomic, 1 op per 16 bytes.
// ---------------------------------------------------------------------------
#define EDGES_PER_WARP 4

__global__ __launch_bounds__(256)
void spmm_kernel(const int* __restrict__ adj_row, const int* __restrict__ adj_col,
                 const float* __restrict__ adj_val, const float* __restrict__ S,
                 float* __restrict__ out, int E) {
    const int warp_id = (blockIdx.x * blockDim.x + threadIdx.x) >> 5;
    const int lane    = threadIdx.x & 31;
    const int e0      = warp_id * EDGES_PER_WARP;
    if (e0 >= E) return;

    int    r[EDGES_PER_WARP];
    float4 m[EDGES_PER_WARP];

    // Gather phase: front-batched loads -> MLP.
#pragma unroll
    for (int i = 0; i < EDGES_PER_WARP; i++) {
        int e = e0 + i;
        if (e < E) {
            int   c = __ldg(adj_col + e);
            float v = __ldg(adj_val + e);
            r[i] = __ldg(adj_row + e);
            float4 s = __ldg((const float4*)(S + (size_t)c * OUT_F) + lane);
            s.x *= v; s.y *= v; s.z *= v; s.w *= v;
            m[i] = s;
        }
    }

    // Scatter phase: no-return vector atomics.
#pragma unroll
    for (int i = 0; i < EDGES_PER_WARP; i++) {
        if (e0 + i < E) {
            float* dst = out + (size_t)r[i] * OUT_F + lane * 4;
            asm volatile("red.global.add.v4.f32 [%0], {%1, %2, %3, %4};"
                         :: "l"(dst), "f"(m[i].x), "f"(m[i].y),
                            "f"(m[i].z), "f"(m[i].w)
                         : "memory");
        }
    }
}

// ---------------------------------------------------------------------------
// Launch: gemm -> init -> spmm (stream-ordered dependencies).
// ---------------------------------------------------------------------------
extern "C" void kernel_launch(void* const* d_in, const int* in_sizes, int n_in,
                              void* d_out, int out_size) {
    const float* X    = (const float*)d_in[0];
    const int*   arow = (const int*)  d_in[1];
    const int*   acol = (const int*)  d_in[2];
    const float* aval = (const float*)d_in[3];
    const float* W    = (const float*)d_in[4];
    const float* bias = (const float*)d_in[5];
    float*       out  = (float*)d_out;

    const int M = in_sizes[0] / IN_F;   // 100000
    const int E = in_sizes[1];          // 1600000

    static float* S = nullptr;
    if (S == nullptr) {
        void* p = nullptr;
        cudaGetSymbolAddress(&p, g_support);
        S = (float*)p;
    }

    // 1) support = X @ W
    gemm_kernel<<<(M + BM - 1) / BM, 256>>>(X, W, S, M);

    // 2) out = bias (broadcast)
    const int n4 = M * (OUT_F / 4);
    init_out_kernel<<<(n4 + 255) / 256, 256>>>(out, bias, n4);

    // 3) out[r] += val * support[c]
    const int nwarps  = (E + EDGES_PER_WARP - 1) / EDGES_PER_WARP;
    const int nblocks = (nwarps + 7) / 8;   // 8 warps / 256-thread block
    spmm_kernel<<<nblocks, 256>>>(arow, acol, aval, S, out, E);
}

// round 13
// speedup vs baseline: 2.2748x; 2.2748x over previous
#include <cuda_runtime.h>
#include <cuda_bf16.h>
#include <cstdint>

// Problem constants (fixed by the reference):
//   N_NODES = 100000, IN_F = 256, OUT_F = 128, N_EDGES = 1600000
// Inputs (metadata order): X_input[f32 N*256], adj_row[i32 E], adj_col[i32 E],
//                          adj_val[f32 E], W[f32 256*128], bias[f32 128]
// Output: f32 [N, 128]

#define MAX_NODES 100000
#define IN_F      256
#define OUT_F     128

// Scratch for support = X @ W  (51.2 MB). Static __device__ per harness rules.
__device__ __align__(16) float g_support[(size_t)MAX_NODES * OUT_F];

// ---------------------------------------------------------------------------
// tf32 helpers
// ---------------------------------------------------------------------------
__device__ __forceinline__ uint32_t f2tf32(float x) {
    uint32_t r;
    asm("cvt.rna.tf32.f32 %0, %1;" : "=r"(r) : "f"(x));
    return r;
}

// D += A(16x8) * B(8x8), tf32 inputs, f32 accum. d aliases c via "+f".
__device__ __forceinline__ void mma_tf32(float& d0, float& d1, float& d2, float& d3,
                                         uint32_t a0, uint32_t a1, uint32_t a2, uint32_t a3,
                                         uint32_t b0, uint32_t b1) {
    asm volatile(
        "mma.sync.aligned.m16n8k8.row.col.f32.tf32.tf32.f32 "
        "{%0,%1,%2,%3}, {%4,%5,%6,%7}, {%8,%9}, {%0,%1,%2,%3};\n"
        : "+f"(d0), "+f"(d1), "+f"(d2), "+f"(d3)
        : "r"(a0), "r"(a1), "r"(a2), "r"(a3), "r"(b0), "r"(b1));
}

// ---------------------------------------------------------------------------
// Kernel 1: tf32 tensor-core GEMM  S[M,128] = X[M,256] @ W[256,128]
// Block tile 128x128, BK=32, 256 threads = 8 warps as 2(m) x 4(n).
// Warp tile 64x32 = 4 m16 tiles x 4 n8 tiles; mma.m16n8k8, fp32 accum.
//
// SMEM (single buffer, fits 48KB static):
//   As[128][44]  row-major M x K, stride 44 floats:
//     - 44*4 B = 176 B, 16B-multiple -> float4 STS aligned
//     - frag a0 banks: ((rb+g)*44 + kb+tig) % 32 = g*12 + tig -> 32 distinct
//   Bs[32][136]  row-major K x N, stride 136 floats:
//     - frag b0 banks: ((kb+tig)*136 + nb+g) % 32 = tig*8 + g -> 32 distinct
// Inputs converted to tf32 (cvt.rna) once at STS time (amortized over reuse).
//
// mma.m16n8k8 tf32 fragment layout (PTX ISA; g = lane>>2, t = lane&3):
//   A: a0=(g,t) a1=(g+8,t) a2=(g,t+4) a3=(g+8,t+4)      [row x k]
//   B: b0=(t,g) b1=(t+4,g)                               [k x col]
//   D: d0=(g,2t) d1=(g,2t+1) d2=(g+8,2t) d3=(g+8,2t+1)
// ---------------------------------------------------------------------------
#define BM 128
#define BN 128
#define BKG 32
#define ASTR 44
#define BSTR 136

__global__ __launch_bounds__(256, 2)
void gemm_tf32_kernel(const float* __restrict__ X, const float* __restrict__ W,
                      float* __restrict__ S, int M) {
    __shared__ float As[BM][ASTR];   // 22528 B
    __shared__ float Bs[BKG][BSTR];  // 17408 B  -> 39.9 KB total

    const int tid  = threadIdx.x;
    const int row0 = blockIdx.x * BM;
    const int warp = tid >> 5, lane = tid & 31;
    const int wm = warp & 1;          // 2 warps along M
    const int wn = warp >> 1;         // 4 warps along N
    const int g  = lane >> 2;         // 0..7
    const int tg = lane & 3;          // 0..3

    float acc[4][4][4];               // [mt][nt][d0..d3]
#pragma unroll
    for (int a = 0; a < 4; a++)
#pragma unroll
        for (int b = 0; b < 4; b++)
#pragma unroll
            for (int c = 0; c < 4; c++) acc[a][b][c] = 0.0f;

    // staging indices: 4 float4 of A + 4 float4 of B per thread per tile
    const int a_row = tid >> 3;            // 0..31  (with +32*i -> 0..127)
    const int a_c4  = tid & 7;             // float4 within 32-wide row
    const int b_kr  = tid >> 5;            // 0..7   (with +8*i -> 0..31)
    const int b_c4  = tid & 31;            // float4 within 128-wide row

    for (int k0 = 0; k0 < IN_F; k0 += BKG) {
        // ---- A tile: 128 rows x 32 k  (4 float4 per thread) ----
#pragma unroll
        for (int i = 0; i < 4; i++) {
            int ar = a_row + i * 32;
            int gr = row0 + ar; if (gr >= M) gr = M - 1;   // clamp (never stored)
            float4 v = *(const float4*)(X + (size_t)gr * IN_F + k0 + a_c4 * 4);
            float4 c;
            c.x = __uint_as_float(f2tf32(v.x));
            c.y = __uint_as_float(f2tf32(v.y));
            c.z = __uint_as_float(f2tf32(v.z));
            c.w = __uint_as_float(f2tf32(v.w));
            *(float4*)&As[ar][a_c4 * 4] = c;
        }
        // ---- B tile: 32 k x 128 n  (4 float4 per thread) ----
#pragma unroll
        for (int i = 0; i < 4; i++) {
            int kr = b_kr + i * 8;
            float4 v = *(const float4*)(W + (size_t)(k0 + kr) * OUT_F + b_c4 * 4);
            float4 c;
            c.x = __uint_as_float(f2tf32(v.x));
            c.y = __uint_as_float(f2tf32(v.y));
            c.z = __uint_as_float(f2tf32(v.z));
            c.w = __uint_as_float(f2tf32(v.w));
            *(float4*)&Bs[kr][b_c4 * 4] = c;
        }
        __syncthreads();

#pragma unroll
        for (int ks = 0; ks < BKG / 8; ks++) {
            const int kb = ks * 8;
            // B fragments for all 4 n-tiles (bank-clean: tig*8 + g)
            uint32_t bf[4][2];
#pragma unroll
            for (int nt = 0; nt < 4; nt++) {
                int nb = wn * 32 + nt * 8;
                bf[nt][0] = __float_as_uint(Bs[kb + tg    ][nb + g]);
                bf[nt][1] = __float_as_uint(Bs[kb + 4 + tg][nb + g]);
            }
#pragma unroll
            for (int mt = 0; mt < 4; mt++) {
                int rb = wm * 64 + mt * 16;
                // A fragment (bank-clean: g*12 + tig)
                uint32_t a0 = __float_as_uint(As[rb + g    ][kb + tg]);
                uint32_t a1 = __float_as_uint(As[rb + 8 + g][kb + tg]);
                uint32_t a2 = __float_as_uint(As[rb + g    ][kb + 4 + tg]);
                uint32_t a3 = __float_as_uint(As[rb + 8 + g][kb + 4 + tg]);
#pragma unroll
                for (int nt = 0; nt < 4; nt++)
                    mma_tf32(acc[mt][nt][0], acc[mt][nt][1],
                             acc[mt][nt][2], acc[mt][nt][3],
                             a0, a1, a2, a3, bf[nt][0], bf[nt][1]);
            }
        }
        __syncthreads();
    }

    // ---- store: d0,d1 at (row_lo, 2t..2t+1), d2,d3 at (row_hi, ...) ----
#pragma unroll
    for (int mt = 0; mt < 4; mt++) {
        int r_lo = row0 + wm * 64 + mt * 16 + g;
        int r_hi = r_lo + 8;
#pragma unroll
        for (int nt = 0; nt < 4; nt++) {
            int col = wn * 32 + nt * 8 + 2 * tg;
            if (r_lo < M) {
                float2 o = make_float2(acc[mt][nt][0], acc[mt][nt][1]);
                *(float2*)(S + (size_t)r_lo * OUT_F + col) = o;
            }
            if (r_hi < M) {
                float2 o = make_float2(acc[mt][nt][2], acc[mt][nt][3]);
                *(float2*)(S + (size_t)r_hi * OUT_F + col) = o;
            }
        }
    }
}

// ---------------------------------------------------------------------------
// Kernel 2: out[n, :] = bias  (broadcast init; out is poisoned by harness)
// ---------------------------------------------------------------------------
__global__ __launch_bounds__(256)
void init_out_kernel(float* __restrict__ out, const float* __restrict__ bias,
                     int n4) {
    int i = blockIdx.x * blockDim.x + threadIdx.x;
    if (i < n4) {
        float4 b = __ldg((const float4*)bias + (i & 31));
        ((float4*)out)[i] = b;
    }
}

// ---------------------------------------------------------------------------
// Kernel 3: COO SpMM (known-good from the 322us run — byte-identical).
// One warp per edge: 32 lanes x float4 = 128 floats (full row).
// 4 edges per warp -> MLP=4 on gathers; support (51.2 MB) is L2-resident.
// red.global.add.v4.f32 = no-return atomic, 1 op per 16 bytes.
// ---------------------------------------------------------------------------
#define EDGES_PER_WARP 4

__global__ __launch_bounds__(256)
void spmm_kernel(const int* __restrict__ adj_row, const int* __restrict__ adj_col,
                 const float* __restrict__ adj_val, const float* __restrict__ S,
                 float* __restrict__ out, int E) {
    const int warp_id = (blockIdx.x * blockDim.x + threadIdx.x) >> 5;
    const int lane    = threadIdx.x & 31;
    const int e0      = warp_id * EDGES_PER_WARP;
    if (e0 >= E) return;

    int    r[EDGES_PER_WARP];
    float4 m[EDGES_PER_WARP];

    // Gather phase: front-batched loads -> MLP.
#pragma unroll
    for (int i = 0; i < EDGES_PER_WARP; i++) {
        int e = e0 + i;
        if (e < E) {
            int   c = __ldg(adj_col + e);
            float v = __ldg(adj_val + e);
            r[i] = __ldg(adj_row + e);
            float4 s = __ldg((const float4*)(S + (size_t)c * OUT_F) + lane);
            s.x *= v; s.y *= v; s.z *= v; s.w *= v;
            m[i] = s;
        }
    }

    // Scatter phase: no-return vector atomics.
#pragma unroll
    for (int i = 0; i < EDGES_PER_WARP; i++) {
        if (e0 + i < E) {
            float* dst = out + (size_t)r[i] * OUT_F + lane * 4;
            asm volatile("red.global.add.v4.f32 [%0], {%1, %2, %3, %4};"
                         :: "l"(dst), "f"(m[i].x), "f"(m[i].y),
                            "f"(m[i].z), "f"(m[i].w)
                         : "memory");
        }
    }
}

// ---------------------------------------------------------------------------
// Launch: gemm -> init -> spmm (stream-ordered dependencies).
// ---------------------------------------------------------------------------
extern "C" void kernel_launch(void* const* d_in, const int* in_sizes, int n_in,
                              void* d_out, int out_size) {
    const float* X    = (const float*)d_in[0];
    const int*   arow = (const int*)  d_in[1];
    const int*   acol = (const int*)  d_in[2];
    const float* aval = (const float*)d_in[3];
    const float* W    = (const float*)d_in[4];
    const float* bias = (const float*)d_in[5];
    float*       out  = (float*)d_out;

    const int M = in_sizes[0] / IN_F;   // 100000
    const int E = in_sizes[1];          // 1600000

    static float* S = nullptr;
    if (S == nullptr) {
        void* p = nullptr;
        cudaGetSymbolAddress(&p, g_support);
        S = (float*)p;
    }

    // 1) support = X @ W   (tf32 tensor cores, fp32 accumulate)
    gemm_tf32_kernel<<<(M + BM - 1) / BM, 256>>>(X, W, S, M);

    // 2) out = bias (broadcast)
    const int n4 = M * (OUT_F / 4);
    init_out_kernel<<<(n4 + 255) / 256, 256>>>(out, bias, n4);

    // 3) out[r] += val * support[c]
    const int nwarps  = (E + EDGES_PER_WARP - 1) / EDGES_PER_WARP;
    const int nblocks = (nwarps + 7) / 8;   // 8 warps / 256-thread block
    spmm_kernel<<<nblocks, 256>>>(arow, acol, aval, S, out, E);
}

// round 14
// speedup vs baseline: 2.8787x; 1.2655x over previous
#include <cuda_runtime.h>
#include <cuda_bf16.h>
#include <cstdint>

// Problem constants (fixed by the reference):
//   N_NODES = 100000, IN_F = 256, OUT_F = 128, N_EDGES = 1600000
// Inputs (metadata order): X_input[f32 N*256], adj_row[i32 E], adj_col[i32 E],
//                          adj_val[f32 E], W[f32 256*128], bias[f32 128]
// Output: f32 [N, 128]

#define MAX_NODES 100000
#define MAX_EDGES 1600000
#define IN_F      256
#define OUT_F     128

// -------------------- static device scratch (no allocs) --------------------
__device__ __align__(16) float g_support[(size_t)MAX_NODES * OUT_F]; // 51.2 MB
__device__ int  g_row_start[MAX_NODES];   // CSR exclusive row offsets
__device__ int  g_row_cnt[MAX_NODES];     // row degrees
__device__ int  g_cursor[MAX_NODES];      // scatter cursors
__device__ int  g_blk_sum[128];           // scan block partials (98 used)
__device__ __align__(8) int2 g_edge[MAX_EDGES];  // packed (col, val_bits)

// ---------------------------------------------------------------------------
// tf32 helpers
// ---------------------------------------------------------------------------
__device__ __forceinline__ uint32_t f2tf32(float x) {
    uint32_t r;
    asm("cvt.rna.tf32.f32 %0, %1;" : "=r"(r) : "f"(x));
    return r;
}

__device__ __forceinline__ void mma_tf32(float& d0, float& d1, float& d2, float& d3,
                                         uint32_t a0, uint32_t a1, uint32_t a2, uint32_t a3,
                                         uint32_t b0, uint32_t b1) {
    asm volatile(
        "mma.sync.aligned.m16n8k8.row.col.f32.tf32.tf32.f32 "
        "{%0,%1,%2,%3}, {%4,%5,%6,%7}, {%8,%9}, {%0,%1,%2,%3};\n"
        : "+f"(d0), "+f"(d1), "+f"(d2), "+f"(d3)
        : "r"(a0), "r"(a1), "r"(a2), "r"(a3), "r"(b0), "r"(b1));
}

// ---------------------------------------------------------------------------
// Kernel 1: tf32 tensor-core GEMM  S[M,128] = X[M,256] @ W[256,128]
// (unchanged from the 59.3us R13 version — proven)
// ---------------------------------------------------------------------------
#define BM 128
#define BN 128
#define BKG 32
#define ASTR 44
#define BSTR 136

__global__ __launch_bounds__(256, 2)
void gemm_tf32_kernel(const float* __restrict__ X, const float* __restrict__ W,
                      float* __restrict__ S, int M) {
    __shared__ float As[BM][ASTR];   // 22528 B
    __shared__ float Bs[BKG][BSTR];  // 17408 B

    const int tid  = threadIdx.x;
    const int row0 = blockIdx.x * BM;
    const int warp = tid >> 5, lane = tid & 31;
    const int wm = warp & 1;          // 2 warps along M
    const int wn = warp >> 1;         // 4 warps along N
    const int g  = lane >> 2;         // 0..7
    const int tg = lane & 3;          // 0..3

    float acc[4][4][4];
#pragma unroll
    for (int a = 0; a < 4; a++)
#pragma unroll
        for (int b = 0; b < 4; b++)
#pragma unroll
            for (int c = 0; c < 4; c++) acc[a][b][c] = 0.0f;

    const int a_row = tid >> 3;
    const int a_c4  = tid & 7;
    const int b_kr  = tid >> 5;
    const int b_c4  = tid & 31;

    for (int k0 = 0; k0 < IN_F; k0 += BKG) {
#pragma unroll
        for (int i = 0; i < 4; i++) {
            int ar = a_row + i * 32;
            int gr = row0 + ar; if (gr >= M) gr = M - 1;
            float4 v = *(const float4*)(X + (size_t)gr * IN_F + k0 + a_c4 * 4);
            float4 c;
            c.x = __uint_as_float(f2tf32(v.x));
            c.y = __uint_as_float(f2tf32(v.y));
            c.z = __uint_as_float(f2tf32(v.z));
            c.w = __uint_as_float(f2tf32(v.w));
            *(float4*)&As[ar][a_c4 * 4] = c;
        }
#pragma unroll
        for (int i = 0; i < 4; i++) {
            int kr = b_kr + i * 8;
            float4 v = *(const float4*)(W + (size_t)(k0 + kr) * OUT_F + b_c4 * 4);
            float4 c;
            c.x = __uint_as_float(f2tf32(v.x));
            c.y = __uint_as_float(f2tf32(v.y));
            c.z = __uint_as_float(f2tf32(v.z));
            c.w = __uint_as_float(f2tf32(v.w));
            *(float4*)&Bs[kr][b_c4 * 4] = c;
        }
        __syncthreads();

#pragma unroll
        for (int ks = 0; ks < BKG / 8; ks++) {
            const int kb = ks * 8;
            uint32_t bf[4][2];
#pragma unroll
            for (int nt = 0; nt < 4; nt++) {
                int nb = wn * 32 + nt * 8;
                bf[nt][0] = __float_as_uint(Bs[kb + tg    ][nb + g]);
                bf[nt][1] = __float_as_uint(Bs[kb + 4 + tg][nb + g]);
            }
#pragma unroll
            for (int mt = 0; mt < 4; mt++) {
                int rb = wm * 64 + mt * 16;
                uint32_t a0 = __float_as_uint(As[rb + g    ][kb + tg]);
                uint32_t a1 = __float_as_uint(As[rb + 8 + g][kb + tg]);
                uint32_t a2 = __float_as_uint(As[rb + g    ][kb + 4 + tg]);
                uint32_t a3 = __float_as_uint(As[rb + 8 + g][kb + 4 + tg]);
#pragma unroll
                for (int nt = 0; nt < 4; nt++)
                    mma_tf32(acc[mt][nt][0], acc[mt][nt][1],
                             acc[mt][nt][2], acc[mt][nt][3],
                             a0, a1, a2, a3, bf[nt][0], bf[nt][1]);
            }
        }
        __syncthreads();
    }

#pragma unroll
    for (int mt = 0; mt < 4; mt++) {
        int r_lo = row0 + wm * 64 + mt * 16 + g;
        int r_hi = r_lo + 8;
#pragma unroll
        for (int nt = 0; nt < 4; nt++) {
            int col = wn * 32 + nt * 8 + 2 * tg;
            if (r_lo < M) {
                float2 o = make_float2(acc[mt][nt][0], acc[mt][nt][1]);
                *(float2*)(S + (size_t)r_lo * OUT_F + col) = o;
            }
            if (r_hi < M) {
                float2 o = make_float2(acc[mt][nt][2], acc[mt][nt][3]);
                *(float2*)(S + (size_t)r_hi * OUT_F + col) = o;
            }
        }
    }
}

// ---------------------------------------------------------------------------
// CSR build. Within-row edge order (cursor atomics) is nondeterministic, which
// only perturbs fp32 summation order (~1e-7) — same property as red.global.
// ---------------------------------------------------------------------------
__global__ void zero_kernel(int N) {
    int i = blockIdx.x * blockDim.x + threadIdx.x;
    if (i < N) { g_row_cnt[i] = 0; g_cursor[i] = 0; }
}

__global__ void hist_kernel(const int* __restrict__ adj_row, int E) {
    int e = blockIdx.x * blockDim.x + threadIdx.x;
    if (e < E) atomicAdd(&g_row_cnt[adj_row[e]], 1);
}

// scan1: per-1024-chunk exclusive scan + chunk totals
__global__ void scan1_kernel(int N) {
    __shared__ int s[1024];
    int t = threadIdx.x;
    int i = blockIdx.x * 1024 + t;
    int v = (i < N) ? g_row_cnt[i] : 0;
    s[t] = v;
    __syncthreads();
#pragma unroll
    for (int off = 1; off < 1024; off <<= 1) {
        int x = (t >= off) ? s[t - off] : 0;
        __syncthreads();
        s[t] += x;
        __syncthreads();
    }
    if (i < N) g_row_start[i] = s[t] - v;
    if (t == 1023) g_blk_sum[blockIdx.x] = s[1023];
}

__global__ void scan2_kernel(int nblk) {
    if (threadIdx.x == 0 && blockIdx.x == 0) {
        int run = 0;
        for (int b = 0; b < nblk; b++) {
            int t = g_blk_sum[b];
            g_blk_sum[b] = run;
            run += t;
        }
    }
}

__global__ void scan3_kernel(int N) {
    int i = blockIdx.x * blockDim.x + threadIdx.x;
    if (i < N) g_row_start[i] += g_blk_sum[i >> 10];
}

// scatter: one packed 8B write per edge (half the transactions of 2 arrays)
__global__ void scatter_kernel(const int* __restrict__ adj_row,
                               const int* __restrict__ adj_col,
                               const float* __restrict__ adj_val, int E) {
    int e = blockIdx.x * blockDim.x + threadIdx.x;
    if (e < E) {
        int r = adj_row[e];
        int pos = g_row_start[r] + atomicAdd(&g_cursor[r], 1);
        g_edge[pos] = make_int2(adj_col[e], __float_as_int(adj_val[e]));
    }
}

// ---------------------------------------------------------------------------
// CSR SpMM: warp per output row, lane owns one float4 of the 128-wide row.
// Row accumulated in registers, written ONCE -> kills the 819 MB atomic
// stream (L2 traffic 1.69 GB -> ~0.9 GB). Gathers stay L2-resident and
// perfectly coalesced (contiguous 512 B per edge). Bias folded in.
// ---------------------------------------------------------------------------
__global__ __launch_bounds__(256)
void spmm_csr_kernel(const float* __restrict__ S, const float* __restrict__ bias,
                     float* __restrict__ out, int N) {
    const int w    = (blockIdx.x * blockDim.x + threadIdx.x) >> 5;
    const int lane = threadIdx.x & 31;
    if (w >= N) return;

    const int start = g_row_start[w];
    const int deg   = g_row_cnt[w];

    float4 acc = __ldg((const float4*)bias + lane);

    int i = 0;
    for (; i + 4 <= deg; i += 4) {
        // front-batched: 4 edge descriptors (broadcast), then 4 gathers (MLP=4)
        int2 e0 = __ldg(g_edge + start + i + 0);
        int2 e1 = __ldg(g_edge + start + i + 1);
        int2 e2 = __ldg(g_edge + start + i + 2);
        int2 e3 = __ldg(g_edge + start + i + 3);
        float4 s0 = __ldg((const float4*)(S + (size_t)e0.x * OUT_F) + lane);
        float4 s1 = __ldg((const float4*)(S + (size_t)e1.x * OUT_F) + lane);
        float4 s2 = __ldg((const float4*)(S + (size_t)e2.x * OUT_F) + lane);
        float4 s3 = __ldg((const float4*)(S + (size_t)e3.x * OUT_F) + lane);
        float v0 = __int_as_float(e0.y), v1 = __int_as_float(e1.y);
        float v2 = __int_as_float(e2.y), v3 = __int_as_float(e3.y);
        acc.x = fmaf(v0, s0.x, acc.x); acc.y = fmaf(v0, s0.y, acc.y);
        acc.z = fmaf(v0, s0.z, acc.z); acc.w = fmaf(v0, s0.w, acc.w);
        acc.x = fmaf(v1, s1.x, acc.x); acc.y = fmaf(v1, s1.y, acc.y);
        acc.z = fmaf(v1, s1.z, acc.z); acc.w = fmaf(v1, s1.w, acc.w);
        acc.x = fmaf(v2, s2.x, acc.x); acc.y = fmaf(v2, s2.y, acc.y);
        acc.z = fmaf(v2, s2.z, acc.z); acc.w = fmaf(v2, s2.w, acc.w);
        acc.x = fmaf(v3, s3.x, acc.x); acc.y = fmaf(v3, s3.y, acc.y);
        acc.z = fmaf(v3, s3.z, acc.z); acc.w = fmaf(v3, s3.w, acc.w);
    }
    for (; i < deg; ++i) {
        int2 e = __ldg(g_edge + start + i);
        float v = __int_as_float(e.y);
        float4 s = __ldg((const float4*)(S + (size_t)e.x * OUT_F) + lane);
        acc.x = fmaf(v, s.x, acc.x); acc.y = fmaf(v, s.y, acc.y);
        acc.z = fmaf(v, s.z, acc.z); acc.w = fmaf(v, s.w, acc.w);
    }

    ((float4*)(out + (size_t)w * OUT_F))[lane] = acc;
}

// ---------------------------------------------------------------------------
// Launch sequence (single stream; all graph-capturable).
// ---------------------------------------------------------------------------
extern "C" void kernel_launch(void* const* d_in, const int* in_sizes, int n_in,
                              void* d_out, int out_size) {
    const float* X    = (const float*)d_in[0];
    const int*   arow = (const int*)  d_in[1];
    const int*   acol = (const int*)  d_in[2];
    const float* aval = (const float*)d_in[3];
    const float* W    = (const float*)d_in[4];
    const float* bias = (const float*)d_in[5];
    float*       out  = (float*)d_out;

    const int M = in_sizes[0] / IN_F;   // 100000
    const int E = in_sizes[1];          // 1600000

    static float* S = nullptr;
    if (S == nullptr) {
        void* p = nullptr;
        cudaGetSymbolAddress(&p, g_support);
        S = (float*)p;
    }

    // 1) support = X @ W   (tf32 tensor cores, fp32 accumulate)
    gemm_tf32_kernel<<<(M + BM - 1) / BM, 256>>>(X, W, S, M);

    // 2) CSR build
    zero_kernel<<<(M + 255) / 256, 256>>>(M);
    hist_kernel<<<(E + 255) / 256, 256>>>(arow, E);
    const int nblk = (M + 1023) / 1024;
    scan1_kernel<<<nblk, 1024>>>(M);
    scan2_kernel<<<1, 32>>>(nblk);
    scan3_kernel<<<(M + 255) / 256, 256>>>(M);
    scatter_kernel<<<(E + 255) / 256, 256>>>(arow, acol, aval, E);

    // 3) out[r,:] = bias + sum_e val_e * support[col_e, :]
    const int nblocks = (M + 7) / 8;   // 8 warps (rows) per 256-thread block
    spmm_csr_kernel<<<nblocks, 256>>>(S, bias, out, M);
}